// round 6
// baseline (speedup 1.0000x reference)
#include <cuda_runtime.h>
#include <stdint.h>

#define BATCH 2
#define SEQ   4096
#define DM    512
#define NH    8
#define DH    64
#define MTOT  (BATCH*SEQ)   // 8192

// Scratch
__device__ float g_Qp[BATCH*NH*SEQ*DH];
__device__ float g_Kp[BATCH*NH*SEQ*DH];
__device__ float g_Vp[BATCH*NH*SEQ*DH];
__device__ float g_At[BATCH*SEQ*DM];
// tf32-preconverted inputs: q | k | v | wq | wk | wv | wo
#define TQ_OFF  0
#define TK_OFF  4194304
#define TV_OFF  8388608
#define TWQ_OFF 12582912
#define TWK_OFF 12845056
#define TWV_OFF 13107200
#define TWO_OFF 13369344
#define T_TOTAL 13631488
__device__ float g_T[T_TOTAL];

// ---------------------------------------------------------------------------
__device__ __forceinline__ unsigned f2tf(float f) {
    unsigned u;
    asm("cvt.rna.tf32.f32 %0, %1;" : "=r"(u) : "f"(f));
    return u;
}
// exp2 on the FMA pipe (no MUFU): magic-number round-to-nearest + degree-5
// Taylor of 2^f on [-0.5, 0.5] (rel err ~2.4e-6), exponent assembled by int add.
// Valid for x <= 0; clamps at -126 (result ~0, FTZ).
__device__ __forceinline__ float fexp2(float x) {
    x = fmaxf(x, -126.f);
    float m = x + 12582912.f;                 // 1.5 * 2^23
    int   e = __float_as_int(m) << 23;        // == round(x) << 23 (mod 2^32)
    float f = x - (m - 12582912.f);           // f in [-0.5, 0.5]
    float p = fmaf(0.0013333558f, f, 0.0096181291f);
    p = fmaf(p, f, 0.055504109f);
    p = fmaf(p, f, 0.24022651f);
    p = fmaf(p, f, 0.69314718f);
    p = fmaf(p, f, 1.0f);
    return __int_as_float(__float_as_int(p) + e);
}
__device__ __forceinline__ void mma_tf32(float* d, const unsigned* a,
                                         unsigned b0, unsigned b1) {
    asm volatile(
        "mma.sync.aligned.m16n8k8.row.col.f32.tf32.tf32.f32 "
        "{%0,%1,%2,%3}, {%4,%5,%6,%7}, {%8,%9}, {%0,%1,%2,%3};\n"
        : "+f"(d[0]), "+f"(d[1]), "+f"(d[2]), "+f"(d[3])
        : "r"(a[0]), "r"(a[1]), "r"(a[2]), "r"(a[3]), "r"(b0), "r"(b1));
}
__device__ __forceinline__ uint32_t smem_u32(const void* p) {
    return (uint32_t)__cvta_generic_to_shared(p);
}
__device__ __forceinline__ void cp16(uint32_t d, const void* s) {
    asm volatile("cp.async.cg.shared.global [%0], [%1], 16;\n" :: "r"(d), "l"(s));
}
#define CP_COMMIT() asm volatile("cp.async.commit_group;\n" ::: "memory")
#define CP_WAIT0()  asm volatile("cp.async.wait_group 0;\n" ::: "memory")
#define CP_WAIT1()  asm volatile("cp.async.wait_group 1;\n" ::: "memory")

// ---------------------------------------------------------------------------
// Pre-convert all inputs to tf32 (RNA) into g_T. float4 grid-stride.
// ---------------------------------------------------------------------------
__global__ void cvt_all(const float* __restrict__ q, const float* __restrict__ k,
                        const float* __restrict__ v, const float* __restrict__ wq,
                        const float* __restrict__ wk, const float* __restrict__ wv,
                        const float* __restrict__ wo)
{
    const int n4 = T_TOTAL / 4;
    float4* dst = (float4*)g_T;
    for (int i = blockIdx.x * blockDim.x + threadIdx.x; i < n4;
         i += gridDim.x * blockDim.x) {
        const float* src; int off4;
        if (i < 1048576)      { src = q; off4 = i; }
        else if (i < 2097152) { src = k; off4 = i - 1048576; }
        else if (i < 3145728) { src = v; off4 = i - 2097152; }
        else {
            int j = i - 3145728;
            int w = j >> 16;
            off4 = j & 65535;
            src = (w == 0) ? wq : (w == 1) ? wk : (w == 2) ? wv : wo;
        }
        float4 x = ((const float4*)src)[off4];
        x.x = __uint_as_float(f2tf(x.x));
        x.y = __uint_as_float(f2tf(x.y));
        x.z = __uint_as_float(f2tf(x.z));
        x.w = __uint_as_float(f2tf(x.w));
        dst[i] = x;
    }
}

// ---------------------------------------------------------------------------
// NT GEMM, cp.async 3-stage pipeline. C[m][n] = sum_k A[m][k]*B[n][k],
// N=K=512, 128x128 tile, BK=32, 128 threads = 4 warps (2x2), warp tile 64x64.
// Dynamic smem: 3 stages x (sA+sB) 128x36 x2 = 110592 B -> 2 CTA/SM.
// OSEL 0: fp32 -> C[m*512+n]; OSEL 1: tf32-round + [B,H,S,Dh] remap.
// ---------------------------------------------------------------------------
template <int OSEL>
__device__ __forceinline__ void gemm_body(const float* __restrict__ A,
                                          const float* __restrict__ B,
                                          float* __restrict__ C)
{
    extern __shared__ float gsm[];
    // stage s: sA = gsm + s*9216, sB = gsm + s*9216 + 4608

    const int tid = threadIdx.x;
    const int lane = tid & 31, wid = tid >> 5;
    const int g = lane >> 2, t = lane & 3;
    const int wm = wid & 1, wn = wid >> 1;
    const int m0 = blockIdx.x << 7;
    const int n0 = blockIdx.y << 7;

    const int r0 = tid >> 3;            // 0..15
    const int c4 = (tid & 7) << 2;      // 0..28

    const uint32_t sbase = smem_u32(gsm);

    auto issue_kb = [&](int kb, int st) {
        uint32_t adst = sbase + (uint32_t)(st * 9216) * 4;
        uint32_t bdst = adst + 4608u * 4;
#pragma unroll
        for (int rr = 0; rr < 8; rr++) {
            int row = r0 + (rr << 4);
            cp16(adst + (uint32_t)(row * 36 + c4) * 4,
                 A + (size_t)(m0 + row) * 512 + kb + c4);
            cp16(bdst + (uint32_t)(row * 36 + c4) * 4,
                 B + (size_t)(n0 + row) * 512 + kb + c4);
        }
        CP_COMMIT();
    };

    float acc[4][8][4];
#pragma unroll
    for (int mt = 0; mt < 4; mt++)
#pragma unroll
        for (int nt = 0; nt < 8; nt++)
#pragma unroll
            for (int c = 0; c < 4; c++) acc[mt][nt][c] = 0.f;

    issue_kb(0, 0);
    issue_kb(32, 1);

    for (int kb = 0; kb < 512; kb += 32) {
        const int it = kb >> 5;
        const int st = it % 3;
        if (kb + 32 >= 512) { CP_WAIT0(); } else { CP_WAIT1(); }
        __syncthreads();
        if (kb + 64 < 512) issue_kb(kb + 64, (it + 2) % 3);

        const float* sA = gsm + st * 9216;
        const float* sB = sA + 4608;

#pragma unroll
        for (int ks = 0; ks < 4; ks++) {
            unsigned af[4][4], bf[8][2];
            const int c = (ks << 3) + t;
#pragma unroll
            for (int mt = 0; mt < 4; mt++) {
                int r = (wm << 6) + (mt << 4) + g;
                af[mt][0] = __float_as_uint(sA[r * 36 + c]);
                af[mt][1] = __float_as_uint(sA[(r + 8) * 36 + c]);
                af[mt][2] = __float_as_uint(sA[r * 36 + c + 4]);
                af[mt][3] = __float_as_uint(sA[(r + 8) * 36 + c + 4]);
            }
#pragma unroll
            for (int nt = 0; nt < 8; nt++) {
                int r = (wn << 6) + (nt << 3) + g;
                bf[nt][0] = __float_as_uint(sB[r * 36 + c]);
                bf[nt][1] = __float_as_uint(sB[r * 36 + c + 4]);
            }
#pragma unroll
            for (int mt = 0; mt < 4; mt++)
#pragma unroll
                for (int nt = 0; nt < 8; nt++)
                    mma_tf32(acc[mt][nt], af[mt], bf[nt][0], bf[nt][1]);
        }
    }

#pragma unroll
    for (int mt = 0; mt < 4; mt++) {
#pragma unroll
        for (int nt = 0; nt < 8; nt++) {
            int m = m0 + (wm << 6) + (mt << 4) + g;
            int n = n0 + (wn << 6) + (nt << 3) + (t << 1);
#pragma unroll
            for (int rh = 0; rh < 2; rh++) {
                int mm = m + (rh << 3);
                float v0 = acc[mt][nt][rh * 2 + 0];
                float v1 = acc[mt][nt][rh * 2 + 1];
                if (OSEL == 0) {
                    C[(size_t)mm * 512 + n]     = v0;
                    C[(size_t)mm * 512 + n + 1] = v1;
                } else {
                    int b = mm >> 12, s = mm & 4095;
                    int h = n >> 6,  d = n & 63;
                    size_t base = (((size_t)(b * NH + h)) * SEQ + s) * DH + d;
                    C[base]     = __uint_as_float(f2tf(v0));
                    C[base + 1] = __uint_as_float(f2tf(v1));
                }
            }
        }
    }
}

__global__ __launch_bounds__(128, 2)
void gemm_proj()
{
    const float* A; const float* B; float* C;
    if (blockIdx.z == 0)      { A = g_T + TQ_OFF; B = g_T + TWQ_OFF; C = g_Qp; }
    else if (blockIdx.z == 1) { A = g_T + TK_OFF; B = g_T + TWK_OFF; C = g_Kp; }
    else                      { A = g_T + TV_OFF; B = g_T + TWV_OFF; C = g_Vp; }
    gemm_body<1>(A, B, C);
}

__global__ __launch_bounds__(128, 2)
void gemm_out(float* __restrict__ out)
{
    gemm_body<0>(g_At, g_T + TWO_OFF, out);
}

// ---------------------------------------------------------------------------
// Flash attention, tf32 mma, cp.async 3-stage K/V pipeline. BQ=128, BK=32,
// 128 threads = 4 warps, warp = 32 q-rows (2 sub-blocks of 16), ks-outer.
// smem (floats): Qs 128x68 @0 | Ps 128x36 @8704 | sK 3x32x68 @13312 |
//                sV 3x32x72 @19840 ; total 26752 fl = 107008 B -> 2 CTA/SM.
// exp2 on FMA pipe (fexp2), no MUFU in softmax.
// ---------------------------------------------------------------------------
__global__ __launch_bounds__(128, 2)
void flash_tc()
{
    extern __shared__ float sm[];
    float* Qs  = sm;                   // [128][68]
    float* Ps  = sm + 8704;            // [128][36]
    float* sKb = sm + 13312;           // [3][32][68]
    float* sVb = sm + 19840;           // [3][32][72]

    const int tid = threadIdx.x;
    const int lane = tid & 31, w = tid >> 5;
    const int g = lane >> 2, t = lane & 3;
    const int qb = (int)(gridDim.x - 1) - (int)blockIdx.x;  // heavy tiles first
    const int q0 = qb << 7;
    const int bh = blockIdx.y;

    const float* Qb = g_Qp + (size_t)bh * SEQ * DH;
    const float* Kb = g_Kp + (size_t)bh * SEQ * DH;
    const float* Vb = g_Vp + (size_t)bh * SEQ * DH;

    const uint32_t sKu = smem_u32(sKb);
    const uint32_t sVu = smem_u32(sVb);

    auto issue_kv = [&](int kt, int buf) {
        const int k0 = kt << 5;
        uint32_t kd = sKu + (uint32_t)(buf * 2176) * 4;
        uint32_t vd = sVu + (uint32_t)(buf * 2304) * 4;
#pragma unroll
        for (int r = 0; r < 4; r++) {
            int j = tid + (r << 7);
            int row = j >> 4, c4 = (j & 15) << 2;
            cp16(kd + (uint32_t)(row * 68 + c4) * 4,
                 Kb + (size_t)(k0 + row) * DH + c4);
            cp16(vd + (uint32_t)(row * 72 + c4) * 4,
                 Vb + (size_t)(k0 + row) * DH + c4);
        }
        CP_COMMIT();
    };

    // stage Q tile 128x64 into Qs (persistent; already tf32 bits)
#pragma unroll
    for (int r = 0; r < 16; r++) {
        int j = tid + (r << 7);
        int row = j >> 4, c4 = (j & 15) << 2;
        *(float4*)&Qs[row * 68 + c4] =
            *(const float4*)(Qb + (size_t)(q0 + row) * DH + c4);
    }

    float o0[8][4], o1[8][4];
#pragma unroll
    for (int nt = 0; nt < 8; nt++)
#pragma unroll
        for (int c = 0; c < 4; c++) { o0[nt][c] = 0.f; o1[nt][c] = 0.f; }
    float mr[4] = {-1e30f, -1e30f, -1e30f, -1e30f};
    float lr[4] = {0.f, 0.f, 0.f, 0.f};

    const float cscale = 0.125f * 1.4426950408889634f;
    const int rw = w << 5;
    const int qrow = rw + g;

    const int ktmax = 4 * qb + 3;      // ktmax >= 3 always
    issue_kv(0, 0);
    issue_kv(1, 1);

    for (int kt = 0; kt <= ktmax; kt++) {
        const int buf = kt % 3;
        if (kt == ktmax) { CP_WAIT0(); } else { CP_WAIT1(); }
        __syncthreads();
        if (kt + 2 <= ktmax) issue_kv(kt + 2, (kt + 2) % 3);

        // warp-level early-out: chunk fully above this warp's diagonal
        const int kvb = kt << 5;
        if (kvb > q0 + rw + 31) continue;

        const float* sK = sKb + buf * 2176;
        const float* sV = sVb + buf * 2304;

        // ---- S = Q K^T (32q x 32kv per warp), ks outer ----
        float s0[4][4], s1[4][4];
#pragma unroll
        for (int nt = 0; nt < 4; nt++)
#pragma unroll
            for (int c = 0; c < 4; c++) { s0[nt][c] = 0.f; s1[nt][c] = 0.f; }
#pragma unroll
        for (int ks = 0; ks < 8; ks++) {
            const int c = (ks << 3) + t;
            unsigned qf0[4], qf1[4];
            qf0[0] = __float_as_uint(Qs[(qrow)      * 68 + c]);
            qf0[1] = __float_as_uint(Qs[(qrow + 8)  * 68 + c]);
            qf0[2] = __float_as_uint(Qs[(qrow)      * 68 + c + 4]);
            qf0[3] = __float_as_uint(Qs[(qrow + 8)  * 68 + c + 4]);
            qf1[0] = __float_as_uint(Qs[(qrow + 16) * 68 + c]);
            qf1[1] = __float_as_uint(Qs[(qrow + 24) * 68 + c]);
            qf1[2] = __float_as_uint(Qs[(qrow + 16) * 68 + c + 4]);
            qf1[3] = __float_as_uint(Qs[(qrow + 24) * 68 + c + 4]);
#pragma unroll
            for (int nt = 0; nt < 4; nt++) {
                int r = (nt << 3) + g;
                unsigned b0 = __float_as_uint(sK[r * 68 + c]);
                unsigned b1 = __float_as_uint(sK[r * 68 + c + 4]);
                mma_tf32(s0[nt], qf0, b0, b1);
                mma_tf32(s1[nt], qf1, b0, b1);
            }
        }

        // ---- scale + causal mask ----
#pragma unroll
        for (int nt = 0; nt < 4; nt++)
#pragma unroll
            for (int c = 0; c < 4; c++) { s0[nt][c] *= cscale; s1[nt][c] *= cscale; }
        if (kt >= 4 * qb) {
            const int qg0 = q0 + qrow;
#pragma unroll
            for (int nt = 0; nt < 4; nt++) {
                int kv = kvb + (nt << 3) + (t << 1);
                if (kv > qg0)          s0[nt][0] = -1e30f;
                if (kv + 1 > qg0)      s0[nt][1] = -1e30f;
                if (kv > qg0 + 8)      s0[nt][2] = -1e30f;
                if (kv + 1 > qg0 + 8)  s0[nt][3] = -1e30f;
                if (kv > qg0 + 16)     s1[nt][0] = -1e30f;
                if (kv + 1 > qg0 + 16) s1[nt][1] = -1e30f;
                if (kv > qg0 + 24)     s1[nt][2] = -1e30f;
                if (kv + 1 > qg0 + 24) s1[nt][3] = -1e30f;
            }
        }

        // ---- online softmax (4 row-sets), exp2 on FMA pipe ----
#pragma unroll
        for (int sb = 0; sb < 2; sb++) {
            float (*s)[4] = sb ? s1 : s0;
            float (*o)[4] = sb ? o1 : o0;
#pragma unroll
            for (int r = 0; r < 2; r++) {
                int ix = sb * 2 + r;
                float mx = -1e30f;
#pragma unroll
                for (int nt = 0; nt < 4; nt++)
                    mx = fmaxf(mx, fmaxf(s[nt][2 * r], s[nt][2 * r + 1]));
                mx = fmaxf(mx, __shfl_xor_sync(0xffffffffu, mx, 1));
                mx = fmaxf(mx, __shfl_xor_sync(0xffffffffu, mx, 2));
                float mn = fmaxf(mr[ix], mx);
                float al = fexp2(mr[ix] - mn);
                mr[ix] = mn;
                float rs = 0.f;
#pragma unroll
                for (int nt = 0; nt < 4; nt++) {
                    float p0 = fexp2(s[nt][2 * r] - mn);
                    float p1 = fexp2(s[nt][2 * r + 1] - mn);
                    s[nt][2 * r] = p0; s[nt][2 * r + 1] = p1;
                    rs += p0 + p1;
                }
                rs += __shfl_xor_sync(0xffffffffu, rs, 1);
                rs += __shfl_xor_sync(0xffffffffu, rs, 2);
                lr[ix] = lr[ix] * al + rs;
#pragma unroll
                for (int nt = 0; nt < 8; nt++) {
                    o[nt][2 * r]     *= al;
                    o[nt][2 * r + 1] *= al;
                }
            }
        }

        // ---- store P (tf32) to warp-private Ps rows ----
#pragma unroll
        for (int sb = 0; sb < 2; sb++) {
            float (*s)[4] = sb ? s1 : s0;
            int rbase = rw + (sb << 4) + g;
#pragma unroll
            for (int nt = 0; nt < 4; nt++) {
                int col = (nt << 3) + (t << 1);
                float2 lo = make_float2(__uint_as_float(f2tf(s[nt][0])),
                                        __uint_as_float(f2tf(s[nt][1])));
                float2 hi = make_float2(__uint_as_float(f2tf(s[nt][2])),
                                        __uint_as_float(f2tf(s[nt][3])));
                *(float2*)&Ps[rbase * 36 + col]       = lo;
                *(float2*)&Ps[(rbase + 8) * 36 + col] = hi;
            }
        }
        __syncwarp();

        // ---- O += P V : ks outer over 32 kv rows ----
#pragma unroll
        for (int ks = 0; ks < 4; ks++) {
            const int c = (ks << 3) + t;
            unsigned pf0[4], pf1[4];
            pf0[0] = __float_as_uint(Ps[(qrow)      * 36 + c]);
            pf0[1] = __float_as_uint(Ps[(qrow + 8)  * 36 + c]);
            pf0[2] = __float_as_uint(Ps[(qrow)      * 36 + c + 4]);
            pf0[3] = __float_as_uint(Ps[(qrow + 8)  * 36 + c + 4]);
            pf1[0] = __float_as_uint(Ps[(qrow + 16) * 36 + c]);
            pf1[1] = __float_as_uint(Ps[(qrow + 24) * 36 + c]);
            pf1[2] = __float_as_uint(Ps[(qrow + 16) * 36 + c + 4]);
            pf1[3] = __float_as_uint(Ps[(qrow + 24) * 36 + c + 4]);
            const int kr = (ks << 3) + t;
#pragma unroll
            for (int nt = 0; nt < 8; nt++) {
                int nc = (nt << 3) + g;
                unsigned v0 = __float_as_uint(sV[kr * 72 + nc]);
                unsigned v1 = __float_as_uint(sV[(kr + 4) * 72 + nc]);
                mma_tf32(o0[nt], pf0, v0, v1);
                mma_tf32(o1[nt], pf1, v0, v1);
            }
        }
    }

    // ---- epilogue -> g_At [B, S, H*Dh], tf32-rounded for gemm_out ----
    const int b = bh >> 3, h = bh & 7;
#pragma unroll
    for (int sb = 0; sb < 2; sb++) {
        float (*o)[4] = sb ? o1 : o0;
#pragma unroll
        for (int r = 0; r < 2; r++) {
            int row = q0 + rw + (sb << 4) + (r << 3) + g;
            float inv = 1.f / lr[sb * 2 + r];
#pragma unroll
            for (int nt = 0; nt < 8; nt++) {
                int col = (h << 6) + (nt << 3) + (t << 1);
                size_t base = ((size_t)b * SEQ + row) * DM + col;
                float2 v = make_float2(
                    __uint_as_float(f2tf(o[nt][2 * r] * inv)),
                    __uint_as_float(f2tf(o[nt][2 * r + 1] * inv)));
                *(float2*)&g_At[base] = v;
            }
        }
    }
}

// ---------------------------------------------------------------------------
extern "C" void kernel_launch(void* const* d_in, const int* in_sizes, int n_in,
                              void* d_out, int out_size)
{
    const float* q  = (const float*)d_in[0];
    const float* k  = (const float*)d_in[1];
    const float* v  = (const float*)d_in[2];
    const float* wq = (const float*)d_in[3];
    const float* wk = (const float*)d_in[4];
    const float* wv = (const float*)d_in[5];
    const float* wo = (const float*)d_in[6];
    float* out = (float*)d_out;

    const int GEMM_SMEM  = 3 * 2 * 128 * 36 * (int)sizeof(float);   // 110592
    const int FLASH_SMEM = 26752 * (int)sizeof(float);              // 107008
    cudaFuncSetAttribute(gemm_proj, cudaFuncAttributeMaxDynamicSharedMemorySize,
                         GEMM_SMEM);
    cudaFuncSetAttribute(gemm_out,  cudaFuncAttributeMaxDynamicSharedMemorySize,
                         GEMM_SMEM);
    cudaFuncSetAttribute(flash_tc,  cudaFuncAttributeMaxDynamicSharedMemorySize,
                         FLASH_SMEM);

    cvt_all<<<1184, 256>>>(q, k, v, wq, wk, wv, wo);

    dim3 pg(MTOT / 128, DM / 128, 3);        // 64 x 4 x 3
    gemm_proj<<<pg, 128, GEMM_SMEM>>>();

    dim3 fg(SEQ / 128, BATCH * NH);          // 32 x 16
    flash_tc<<<fg, 128, FLASH_SMEM>>>();

    dim3 og(MTOT / 128, DM / 128);           // 64 x 4
    gemm_out<<<og, 128, GEMM_SMEM>>>(out);
}

// round 7
// speedup vs baseline: 1.1459x; 1.1459x over previous
#include <cuda_runtime.h>

#define BATCH 2
#define SEQ   4096
#define DM    512
#define NH    8
#define DH    64
#define MTOT  (BATCH*SEQ)   // 8192

// Scratch: projected Q/K/V (tf32-rounded fp32 bits) in [B,H,S,Dh], attn out [B,S,D]
__device__ float g_Qp[BATCH*NH*SEQ*DH];
__device__ float g_Kp[BATCH*NH*SEQ*DH];
__device__ float g_Vp[BATCH*NH*SEQ*DH];
__device__ float g_At[BATCH*SEQ*DM];

// ---------------------------------------------------------------------------
__device__ __forceinline__ unsigned f2tf(float f) {
    unsigned u;
    asm("cvt.rna.tf32.f32 %0, %1;" : "=r"(u) : "f"(f));
    return u;
}
__device__ __forceinline__ float ex2_(float x) {
    float y;
    asm("ex2.approx.f32 %0, %1;" : "=f"(y) : "f"(x));
    return y;
}
__device__ __forceinline__ void mma_tf32(float* d, const unsigned* a,
                                         unsigned b0, unsigned b1) {
    asm volatile(
        "mma.sync.aligned.m16n8k8.row.col.f32.tf32.tf32.f32 "
        "{%0,%1,%2,%3}, {%4,%5,%6,%7}, {%8,%9}, {%0,%1,%2,%3};\n"
        : "+f"(d[0]), "+f"(d[1]), "+f"(d[2]), "+f"(d[3])
        : "r"(a[0]), "r"(a[1]), "r"(a[2]), "r"(a[3]), "r"(b0), "r"(b1));
}

// ---------------------------------------------------------------------------
// NT GEMM (Round-4 config, measured fastest): C[m][n] = sum_k A[m][k]*B[n][k],
// N=K=512. 128x128 tile, BK=32, 128 threads = 4 warps (2x2), warp tile 64x64.
// Sync staging with tf32 convert. OSEL 0: fp32 -> C[m*512+n];
// OSEL 1: tf32-round + [B,H,S,Dh] remap.
// ---------------------------------------------------------------------------
template <int OSEL>
__device__ __forceinline__ void gemm_body(const float* __restrict__ A,
                                          const float* __restrict__ B,
                                          float* __restrict__ C)
{
    __shared__ float sA[128][36];
    __shared__ float sB[128][36];

    const int tid = threadIdx.x;
    const int lane = tid & 31, wid = tid >> 5;
    const int g = lane >> 2, t = lane & 3;
    const int wm = wid & 1, wn = wid >> 1;          // 2x2 warp grid
    const int m0 = blockIdx.x << 7;
    const int n0 = blockIdx.y << 7;

    float acc[4][8][4];
#pragma unroll
    for (int mt = 0; mt < 4; mt++)
#pragma unroll
        for (int nt = 0; nt < 8; nt++)
#pragma unroll
            for (int c = 0; c < 4; c++) acc[mt][nt][c] = 0.f;

    const int r0 = tid >> 3;            // 0..15
    const int c4 = (tid & 7) << 2;      // 0..28 step 4

    for (int kb = 0; kb < 512; kb += 32) {
#pragma unroll
        for (int rr = 0; rr < 8; rr++) {
            int row = r0 + (rr << 4);
            float4 va = *(const float4*)(A + (size_t)(m0 + row) * 512 + kb + c4);
            float4 ta;
            ta.x = __uint_as_float(f2tf(va.x));
            ta.y = __uint_as_float(f2tf(va.y));
            ta.z = __uint_as_float(f2tf(va.z));
            ta.w = __uint_as_float(f2tf(va.w));
            *(float4*)&sA[row][c4] = ta;
            float4 vb = *(const float4*)(B + (size_t)(n0 + row) * 512 + kb + c4);
            float4 tb;
            tb.x = __uint_as_float(f2tf(vb.x));
            tb.y = __uint_as_float(f2tf(vb.y));
            tb.z = __uint_as_float(f2tf(vb.z));
            tb.w = __uint_as_float(f2tf(vb.w));
            *(float4*)&sB[row][c4] = tb;
        }
        __syncthreads();

#pragma unroll
        for (int ks = 0; ks < 4; ks++) {
            unsigned af[4][4], bf[8][2];
#pragma unroll
            for (int mt = 0; mt < 4; mt++) {
                int r = (wm << 6) + (mt << 4) + g;
                int c = (ks << 3) + t;
                af[mt][0] = __float_as_uint(sA[r][c]);
                af[mt][1] = __float_as_uint(sA[r + 8][c]);
                af[mt][2] = __float_as_uint(sA[r][c + 4]);
                af[mt][3] = __float_as_uint(sA[r + 8][c + 4]);
            }
#pragma unroll
            for (int nt = 0; nt < 8; nt++) {
                int r = (wn << 6) + (nt << 3) + g;
                int c = (ks << 3) + t;
                bf[nt][0] = __float_as_uint(sB[r][c]);
                bf[nt][1] = __float_as_uint(sB[r][c + 4]);
            }
#pragma unroll
            for (int mt = 0; mt < 4; mt++)
#pragma unroll
                for (int nt = 0; nt < 8; nt++)
                    mma_tf32(acc[mt][nt], af[mt], bf[nt][0], bf[nt][1]);
        }
        __syncthreads();
    }

#pragma unroll
    for (int mt = 0; mt < 4; mt++) {
#pragma unroll
        for (int nt = 0; nt < 8; nt++) {
            int m = m0 + (wm << 6) + (mt << 4) + g;
            int n = n0 + (wn << 6) + (nt << 3) + (t << 1);
#pragma unroll
            for (int rh = 0; rh < 2; rh++) {
                int mm = m + (rh << 3);
                float v0 = acc[mt][nt][rh * 2 + 0];
                float v1 = acc[mt][nt][rh * 2 + 1];
                if (OSEL == 0) {
                    C[(size_t)mm * 512 + n]     = v0;
                    C[(size_t)mm * 512 + n + 1] = v1;
                } else {
                    int b = mm >> 12, s = mm & 4095;
                    int h = n >> 6,  d = n & 63;
                    size_t base = (((size_t)(b * NH + h)) * SEQ + s) * DH + d;
                    C[base]     = __uint_as_float(f2tf(v0));
                    C[base + 1] = __uint_as_float(f2tf(v1));
                }
            }
        }
    }
}

__global__ __launch_bounds__(128, 2)
void gemm_proj(const float* __restrict__ q, const float* __restrict__ k,
               const float* __restrict__ v, const float* __restrict__ wq,
               const float* __restrict__ wk, const float* __restrict__ wv)
{
    const float* A; const float* B; float* C;
    if (blockIdx.z == 0)      { A = q; B = wq; C = g_Qp; }
    else if (blockIdx.z == 1) { A = k; B = wk; C = g_Kp; }
    else                      { A = v; B = wv; C = g_Vp; }
    gemm_body<1>(A, B, C);
}

__global__ __launch_bounds__(128, 2)
void gemm_out(const float* __restrict__ wo, float* __restrict__ out)
{
    gemm_body<0>(g_At, wo, out);
}

// ---------------------------------------------------------------------------
// Flash attention, tf32 mma. BQ=128, BK=32, 128 threads = 4 warps,
// warp = 32 q-rows (2 sub-blocks of 16), ks-outer. Sync K/V staging.
// smem (floats): Qs 128x68 @0 | Ps 128x36 @8704 | sK 32x68 @13312 |
//                sV 32x72 @15488 ; total 17792 fl = 71168 B -> 3 CTA/SM.
// ---------------------------------------------------------------------------
__global__ __launch_bounds__(128, 3)
void flash_tc()
{
    extern __shared__ float sm[];
    float* Qs = sm;                    // [128][68]
    float* Ps = sm + 8704;             // [128][36]
    float* sK = sm + 13312;            // [32][68]
    float* sV = sm + 15488;            // [32][72]

    const int tid = threadIdx.x;
    const int lane = tid & 31, w = tid >> 5;
    const int g = lane >> 2, t = lane & 3;
    const int qb = (int)(gridDim.x - 1) - (int)blockIdx.x;  // heavy tiles first
    const int q0 = qb << 7;
    const int bh = blockIdx.y;

    const float* Qb = g_Qp + (size_t)bh * SEQ * DH;
    const float* Kb = g_Kp + (size_t)bh * SEQ * DH;
    const float* Vb = g_Vp + (size_t)bh * SEQ * DH;

    // stage Q tile 128x64 into Qs (persistent; already tf32 bits)
#pragma unroll
    for (int r = 0; r < 16; r++) {
        int j = tid + (r << 7);
        int row = j >> 4, c4 = (j & 15) << 2;
        *(float4*)&Qs[row * 68 + c4] =
            *(const float4*)(Qb + (size_t)(q0 + row) * DH + c4);
    }

    float o0[8][4], o1[8][4];
#pragma unroll
    for (int nt = 0; nt < 8; nt++)
#pragma unroll
        for (int c = 0; c < 4; c++) { o0[nt][c] = 0.f; o1[nt][c] = 0.f; }
    float mr[4] = {-1e30f, -1e30f, -1e30f, -1e30f};
    float lr[4] = {0.f, 0.f, 0.f, 0.f};

    const float cscale = 0.125f * 1.4426950408889634f;  // 1/sqrt(64) * log2(e)
    const int rw = w << 5;
    const int qrow = rw + g;

    const int ktmax = 4 * qb + 3;
    for (int kt = 0; kt <= ktmax; kt++) {
        __syncthreads();               // prior sK/sV reads done (also Q stage)
        {   // stage K, V chunk (32x64 each)
            const int k0 = kt << 5;
#pragma unroll
            for (int r = 0; r < 4; r++) {
                int j = tid + (r << 7);
                int row = j >> 4, c4 = (j & 15) << 2;
                *(float4*)&sK[row * 68 + c4] =
                    *(const float4*)(Kb + (size_t)(k0 + row) * DH + c4);
                *(float4*)&sV[row * 72 + c4] =
                    *(const float4*)(Vb + (size_t)(k0 + row) * DH + c4);
            }
        }
        __syncthreads();

        // warp-level early-out: chunk fully above this warp's diagonal
        const int kvb = kt << 5;
        if (kvb > q0 + rw + 31) continue;

        // ---- S = Q K^T (32q x 32kv per warp), ks outer ----
        float s0[4][4], s1[4][4];
#pragma unroll
        for (int nt = 0; nt < 4; nt++)
#pragma unroll
            for (int c = 0; c < 4; c++) { s0[nt][c] = 0.f; s1[nt][c] = 0.f; }
#pragma unroll
        for (int ks = 0; ks < 8; ks++) {
            const int c = (ks << 3) + t;
            unsigned qf0[4], qf1[4];
            qf0[0] = __float_as_uint(Qs[(qrow)      * 68 + c]);
            qf0[1] = __float_as_uint(Qs[(qrow + 8)  * 68 + c]);
            qf0[2] = __float_as_uint(Qs[(qrow)      * 68 + c + 4]);
            qf0[3] = __float_as_uint(Qs[(qrow + 8)  * 68 + c + 4]);
            qf1[0] = __float_as_uint(Qs[(qrow + 16) * 68 + c]);
            qf1[1] = __float_as_uint(Qs[(qrow + 24) * 68 + c]);
            qf1[2] = __float_as_uint(Qs[(qrow + 16) * 68 + c + 4]);
            qf1[3] = __float_as_uint(Qs[(qrow + 24) * 68 + c + 4]);
#pragma unroll
            for (int nt = 0; nt < 4; nt++) {
                int r = (nt << 3) + g;
                unsigned b0 = __float_as_uint(sK[r * 68 + c]);
                unsigned b1 = __float_as_uint(sK[r * 68 + c + 4]);
                mma_tf32(s0[nt], qf0, b0, b1);
                mma_tf32(s1[nt], qf1, b0, b1);
            }
        }

        // ---- scale + causal mask ----
#pragma unroll
        for (int nt = 0; nt < 4; nt++)
#pragma unroll
            for (int c = 0; c < 4; c++) { s0[nt][c] *= cscale; s1[nt][c] *= cscale; }
        if (kt >= 4 * qb) {
            const int qg0 = q0 + qrow;
#pragma unroll
            for (int nt = 0; nt < 4; nt++) {
                int kv = kvb + (nt << 3) + (t << 1);
                if (kv > qg0)          s0[nt][0] = -1e30f;
                if (kv + 1 > qg0)      s0[nt][1] = -1e30f;
                if (kv > qg0 + 8)      s0[nt][2] = -1e30f;
                if (kv + 1 > qg0 + 8)  s0[nt][3] = -1e30f;
                if (kv > qg0 + 16)     s1[nt][0] = -1e30f;
                if (kv + 1 > qg0 + 16) s1[nt][1] = -1e30f;
                if (kv > qg0 + 24)     s1[nt][2] = -1e30f;
                if (kv + 1 > qg0 + 24) s1[nt][3] = -1e30f;
            }
        }

        // ---- online softmax (4 row-sets) ----
#pragma unroll
        for (int sb = 0; sb < 2; sb++) {
            float (*s)[4] = sb ? s1 : s0;
            float (*o)[4] = sb ? o1 : o0;
#pragma unroll
            for (int r = 0; r < 2; r++) {
                int ix = sb * 2 + r;
                float mx = -1e30f;
#pragma unroll
                for (int nt = 0; nt < 4; nt++)
                    mx = fmaxf(mx, fmaxf(s[nt][2 * r], s[nt][2 * r + 1]));
                mx = fmaxf(mx, __shfl_xor_sync(0xffffffffu, mx, 1));
                mx = fmaxf(mx, __shfl_xor_sync(0xffffffffu, mx, 2));
                float mn = fmaxf(mr[ix], mx);
                float al = ex2_(mr[ix] - mn);
                mr[ix] = mn;
                float rs = 0.f;
#pragma unroll
                for (int nt = 0; nt < 4; nt++) {
                    float p0 = ex2_(s[nt][2 * r] - mn);
                    float p1 = ex2_(s[nt][2 * r + 1] - mn);
                    s[nt][2 * r] = p0; s[nt][2 * r + 1] = p1;
                    rs += p0 + p1;
                }
                rs += __shfl_xor_sync(0xffffffffu, rs, 1);
                rs += __shfl_xor_sync(0xffffffffu, rs, 2);
                lr[ix] = lr[ix] * al + rs;
#pragma unroll
                for (int nt = 0; nt < 8; nt++) {
                    o[nt][2 * r]     *= al;
                    o[nt][2 * r + 1] *= al;
                }
            }
        }

        // ---- store P (tf32) to warp-private Ps rows ----
#pragma unroll
        for (int sb = 0; sb < 2; sb++) {
            float (*s)[4] = sb ? s1 : s0;
            int rbase = rw + (sb << 4) + g;
#pragma unroll
            for (int nt = 0; nt < 4; nt++) {
                int col = (nt << 3) + (t << 1);
                float2 lo = make_float2(__uint_as_float(f2tf(s[nt][0])),
                                        __uint_as_float(f2tf(s[nt][1])));
                float2 hi = make_float2(__uint_as_float(f2tf(s[nt][2])),
                                        __uint_as_float(f2tf(s[nt][3])));
                *(float2*)&Ps[rbase * 36 + col]       = lo;
                *(float2*)&Ps[(rbase + 8) * 36 + col] = hi;
            }
        }
        __syncwarp();

        // ---- O += P V : ks outer over 32 kv rows ----
#pragma unroll
        for (int ks = 0; ks < 4; ks++) {
            const int c = (ks << 3) + t;
            unsigned pf0[4], pf1[4];
            pf0[0] = __float_as_uint(Ps[(qrow)      * 36 + c]);
            pf0[1] = __float_as_uint(Ps[(qrow + 8)  * 36 + c]);
            pf0[2] = __float_as_uint(Ps[(qrow)      * 36 + c + 4]);
            pf0[3] = __float_as_uint(Ps[(qrow + 8)  * 36 + c + 4]);
            pf1[0] = __float_as_uint(Ps[(qrow + 16) * 36 + c]);
            pf1[1] = __float_as_uint(Ps[(qrow + 24) * 36 + c]);
            pf1[2] = __float_as_uint(Ps[(qrow + 16) * 36 + c + 4]);
            pf1[3] = __float_as_uint(Ps[(qrow + 24) * 36 + c + 4]);
            const int kr = (ks << 3) + t;
#pragma unroll
            for (int nt = 0; nt < 8; nt++) {
                int nc = (nt << 3) + g;
                unsigned v0 = __float_as_uint(sV[kr * 72 + nc]);
                unsigned v1 = __float_as_uint(sV[(kr + 4) * 72 + nc]);
                mma_tf32(o0[nt], pf0, v0, v1);
                mma_tf32(o1[nt], pf1, v0, v1);
            }
        }
    }

    // ---- epilogue -> g_At [B, S, H*Dh] (plain fp32, as in R4) ----
    const int b = bh >> 3, h = bh & 7;
#pragma unroll
    for (int sb = 0; sb < 2; sb++) {
        float (*o)[4] = sb ? o1 : o0;
#pragma unroll
        for (int r = 0; r < 2; r++) {
            int row = q0 + rw + (sb << 4) + (r << 3) + g;
            float inv = 1.f / lr[sb * 2 + r];
#pragma unroll
            for (int nt = 0; nt < 8; nt++) {
                int col = (h << 6) + (nt << 3) + (t << 1);
                size_t base = ((size_t)b * SEQ + row) * DM + col;
                float2 v = make_float2(o[nt][2 * r] * inv, o[nt][2 * r + 1] * inv);
                *(float2*)&g_At[base] = v;
            }
        }
    }
}

// ---------------------------------------------------------------------------
extern "C" void kernel_launch(void* const* d_in, const int* in_sizes, int n_in,
                              void* d_out, int out_size)
{
    const float* q  = (const float*)d_in[0];
    const float* k  = (const float*)d_in[1];
    const float* v  = (const float*)d_in[2];
    const float* wq = (const float*)d_in[3];
    const float* wk = (const float*)d_in[4];
    const float* wv = (const float*)d_in[5];
    const float* wo = (const float*)d_in[6];
    float* out = (float*)d_out;

    const int FLASH_SMEM = 17792 * (int)sizeof(float);   // 71168 B -> 3 CTA/SM
    cudaFuncSetAttribute(flash_tc, cudaFuncAttributeMaxDynamicSharedMemorySize,
                         FLASH_SMEM);

    dim3 pg(MTOT / 128, DM / 128, 3);        // 64 x 4 x 3
    gemm_proj<<<pg, 128>>>(q, k, v, wq, wk, wv);

    dim3 fg(SEQ / 128, BATCH * NH);          // 32 x 16
    flash_tc<<<fg, 128, FLASH_SMEM>>>();

    dim3 og(MTOT / 128, DM / 128);           // 64 x 4
    gemm_out<<<og, 128>>>(wo, out);
}

// round 8
// speedup vs baseline: 1.1872x; 1.0360x over previous
#include <cuda_runtime.h>

#define BATCH 2
#define SEQ   4096
#define DM    512
#define NH    8
#define DH    64
#define MTOT  (BATCH*SEQ)   // 8192

// Scratch: projected Q/K/V (tf32-rounded fp32 bits) in [B,H,S,Dh], attn out [B,S,D]
__device__ float g_Qp[BATCH*NH*SEQ*DH];
__device__ float g_Kp[BATCH*NH*SEQ*DH];
__device__ float g_Vp[BATCH*NH*SEQ*DH];
__device__ float g_At[BATCH*SEQ*DM];

// ---------------------------------------------------------------------------
__device__ __forceinline__ unsigned f2tf(float f) {
    unsigned u;
    asm("cvt.rna.tf32.f32 %0, %1;" : "=r"(u) : "f"(f));
    return u;
}
__device__ __forceinline__ float ex2_(float x) {
    float y;
    asm("ex2.approx.f32 %0, %1;" : "=f"(y) : "f"(x));
    return y;
}
__device__ __forceinline__ void mma_tf32(float* d, const unsigned* a,
                                         unsigned b0, unsigned b1) {
    asm volatile(
        "mma.sync.aligned.m16n8k8.row.col.f32.tf32.tf32.f32 "
        "{%0,%1,%2,%3}, {%4,%5,%6,%7}, {%8,%9}, {%0,%1,%2,%3};\n"
        : "+f"(d[0]), "+f"(d[1]), "+f"(d[2]), "+f"(d[3])
        : "r"(a[0]), "r"(a[1]), "r"(a[2]), "r"(a[3]), "r"(b0), "r"(b1));
}

// ---------------------------------------------------------------------------
// NT GEMM (Round-4 config, measured fastest) — unchanged this round.
// ---------------------------------------------------------------------------
template <int OSEL>
__device__ __forceinline__ void gemm_body(const float* __restrict__ A,
                                          const float* __restrict__ B,
                                          float* __restrict__ C)
{
    __shared__ float sA[128][36];
    __shared__ float sB[128][36];

    const int tid = threadIdx.x;
    const int lane = tid & 31, wid = tid >> 5;
    const int g = lane >> 2, t = lane & 3;
    const int wm = wid & 1, wn = wid >> 1;          // 2x2 warp grid
    const int m0 = blockIdx.x << 7;
    const int n0 = blockIdx.y << 7;

    float acc[4][8][4];
#pragma unroll
    for (int mt = 0; mt < 4; mt++)
#pragma unroll
        for (int nt = 0; nt < 8; nt++)
#pragma unroll
            for (int c = 0; c < 4; c++) acc[mt][nt][c] = 0.f;

    const int r0 = tid >> 3;            // 0..15
    const int c4 = (tid & 7) << 2;      // 0..28 step 4

    for (int kb = 0; kb < 512; kb += 32) {
#pragma unroll
        for (int rr = 0; rr < 8; rr++) {
            int row = r0 + (rr << 4);
            float4 va = *(const float4*)(A + (size_t)(m0 + row) * 512 + kb + c4);
            float4 ta;
            ta.x = __uint_as_float(f2tf(va.x));
            ta.y = __uint_as_float(f2tf(va.y));
            ta.z = __uint_as_float(f2tf(va.z));
            ta.w = __uint_as_float(f2tf(va.w));
            *(float4*)&sA[row][c4] = ta;
            float4 vb = *(const float4*)(B + (size_t)(n0 + row) * 512 + kb + c4);
            float4 tb;
            tb.x = __uint_as_float(f2tf(vb.x));
            tb.y = __uint_as_float(f2tf(vb.y));
            tb.z = __uint_as_float(f2tf(vb.z));
            tb.w = __uint_as_float(f2tf(vb.w));
            *(float4*)&sB[row][c4] = tb;
        }
        __syncthreads();

#pragma unroll
        for (int ks = 0; ks < 4; ks++) {
            unsigned af[4][4], bf[8][2];
#pragma unroll
            for (int mt = 0; mt < 4; mt++) {
                int r = (wm << 6) + (mt << 4) + g;
                int c = (ks << 3) + t;
                af[mt][0] = __float_as_uint(sA[r][c]);
                af[mt][1] = __float_as_uint(sA[r + 8][c]);
                af[mt][2] = __float_as_uint(sA[r][c + 4]);
                af[mt][3] = __float_as_uint(sA[r + 8][c + 4]);
            }
#pragma unroll
            for (int nt = 0; nt < 8; nt++) {
                int r = (wn << 6) + (nt << 3) + g;
                int c = (ks << 3) + t;
                bf[nt][0] = __float_as_uint(sB[r][c]);
                bf[nt][1] = __float_as_uint(sB[r][c + 4]);
            }
#pragma unroll
            for (int mt = 0; mt < 4; mt++)
#pragma unroll
                for (int nt = 0; nt < 8; nt++)
                    mma_tf32(acc[mt][nt], af[mt], bf[nt][0], bf[nt][1]);
        }
        __syncthreads();
    }

#pragma unroll
    for (int mt = 0; mt < 4; mt++) {
#pragma unroll
        for (int nt = 0; nt < 8; nt++) {
            int m = m0 + (wm << 6) + (mt << 4) + g;
            int n = n0 + (wn << 6) + (nt << 3) + (t << 1);
#pragma unroll
            for (int rh = 0; rh < 2; rh++) {
                int mm = m + (rh << 3);
                float v0 = acc[mt][nt][rh * 2 + 0];
                float v1 = acc[mt][nt][rh * 2 + 1];
                if (OSEL == 0) {
                    C[(size_t)mm * 512 + n]     = v0;
                    C[(size_t)mm * 512 + n + 1] = v1;
                } else {
                    int b = mm >> 12, s = mm & 4095;
                    int h = n >> 6,  d = n & 63;
                    size_t base = (((size_t)(b * NH + h)) * SEQ + s) * DH + d;
                    C[base]     = __uint_as_float(f2tf(v0));
                    C[base + 1] = __uint_as_float(f2tf(v1));
                }
            }
        }
    }
}

__global__ __launch_bounds__(128, 2)
void gemm_proj(const float* __restrict__ q, const float* __restrict__ k,
               const float* __restrict__ v, const float* __restrict__ wq,
               const float* __restrict__ wk, const float* __restrict__ wv)
{
    const float* A; const float* B; float* C;
    if (blockIdx.z == 0)      { A = q; B = wq; C = g_Qp; }
    else if (blockIdx.z == 1) { A = k; B = wk; C = g_Kp; }
    else                      { A = v; B = wv; C = g_Vp; }
    gemm_body<1>(A, B, C);
}

__global__ __launch_bounds__(128, 2)
void gemm_out(const float* __restrict__ wo, float* __restrict__ out)
{
    gemm_body<0>(g_At, wo, out);
}

// ---------------------------------------------------------------------------
// Flash attention, tf32 mma. BQ=128, BK=32, 128 threads = 4 warps,
// warp = 32 q-rows (2 sub-blocks of 16), ks-outer. Sync K/V staging.
// NEW: Q and P stored in a-fragment order so operand fetch is LDS.128:
//   Qs: 64 blocks (mt2 0..7, ks 0..7) x 32 lanes x 4 fl; block = mt2*8+ks.
//       f4 at lane (g,t) = {Q[16mt2+g][8ks+t], Q[16mt2+8+g][8ks+t],
//                           Q[16mt2+g][8ks+t+4], Q[16mt2+8+g][8ks+t+4]}
//   Ps: 32 blocks (mt2 0..7, ks 0..3) x 32 lanes x 4 fl; block = mt2*4+ks.
// smem (floats): Qs 8192 @0 | Ps 4096 @8192 | sK 32x68 @12288 |
//                sV 32x72 @14464 ; total 16768 fl = 67072 B -> 3 CTA/SM.
// ---------------------------------------------------------------------------
__global__ __launch_bounds__(128, 3)
void flash_tc()
{
    extern __shared__ float sm[];
    float* Qs = sm;                    // frag-order, 8192 fl
    float* Ps = sm + 8192;             // frag-order, 4096 fl
    float* sK = sm + 12288;            // [32][68]
    float* sV = sm + 14464;            // [32][72]
    const float4* QsF4 = (const float4*)Qs;
    const float4* PsF4 = (const float4*)Ps;

    const int tid = threadIdx.x;
    const int lane = tid & 31, w = tid >> 5;
    const int g = lane >> 2, t = lane & 3;
    const int qb = (int)(gridDim.x - 1) - (int)blockIdx.x;  // heavy tiles first
    const int q0 = qb << 7;
    const int bh = blockIdx.y;

    const float* Qb = g_Qp + (size_t)bh * SEQ * DH;
    const float* Kb = g_Kp + (size_t)bh * SEQ * DH;
    const float* Vb = g_Vp + (size_t)bh * SEQ * DH;

    // stage Q tile 128x64 into Qs in a-frag order (once per CTA)
#pragma unroll
    for (int r = 0; r < 16; r++) {
        int j = tid + (r << 7);
        int row = j >> 4, c4 = (j & 15) << 2;
        float4 vq = *(const float4*)(Qb + (size_t)(q0 + row) * DH + c4);
        int mt2 = row >> 4, rbit = (row >> 3) & 1, gg = row & 7;
        int ks = c4 >> 3, hbit = (c4 >> 2) & 1;
        int base = ((mt2 << 3) + ks) * 128 + (gg << 4) + rbit + (hbit << 1);
        Qs[base]      = vq.x;
        Qs[base + 4]  = vq.y;
        Qs[base + 8]  = vq.z;
        Qs[base + 12] = vq.w;
    }

    float o0[8][4], o1[8][4];
#pragma unroll
    for (int nt = 0; nt < 8; nt++)
#pragma unroll
        for (int c = 0; c < 4; c++) { o0[nt][c] = 0.f; o1[nt][c] = 0.f; }
    float mr[4] = {-1e30f, -1e30f, -1e30f, -1e30f};
    float lr[4] = {0.f, 0.f, 0.f, 0.f};

    const float cscale = 0.125f * 1.4426950408889634f;  // 1/sqrt(64) * log2(e)
    const int rw = w << 5;
    // P-store helpers (c-frag -> a-frag mapping), per-lane constants
    const int tp = (t < 2) ? (t << 1) : ((t << 1) - 4);
    const int ep = (t < 2) ? 0 : 2;

    const int ktmax = 4 * qb + 3;
    for (int kt = 0; kt <= ktmax; kt++) {
        __syncthreads();               // prior sK/sV reads done (also Q stage)
        {   // stage K, V chunk (32x64 each), row-major padded
            const int k0 = kt << 5;
#pragma unroll
            for (int r = 0; r < 4; r++) {
                int j = tid + (r << 7);
                int row = j >> 4, c4 = (j & 15) << 2;
                *(float4*)&sK[row * 68 + c4] =
                    *(const float4*)(Kb + (size_t)(k0 + row) * DH + c4);
                *(float4*)&sV[row * 72 + c4] =
                    *(const float4*)(Vb + (size_t)(k0 + row) * DH + c4);
            }
        }
        __syncthreads();

        // warp-level early-out: chunk fully above this warp's diagonal
        const int kvb = kt << 5;
        if (kvb > q0 + rw + 31) continue;

        // ---- S = Q K^T (32q x 32kv per warp), ks outer, LDS.128 Q frags ----
        float s0[4][4], s1[4][4];
#pragma unroll
        for (int nt = 0; nt < 4; nt++)
#pragma unroll
            for (int c = 0; c < 4; c++) { s0[nt][c] = 0.f; s1[nt][c] = 0.f; }
#pragma unroll
        for (int ks = 0; ks < 8; ks++) {
            const int c = (ks << 3) + t;
            float4 qv0 = QsF4[(((w << 1) << 3) + ks) * 32 + lane];
            float4 qv1 = QsF4[((((w << 1) + 1) << 3) + ks) * 32 + lane];
            unsigned qf0[4] = {__float_as_uint(qv0.x), __float_as_uint(qv0.y),
                               __float_as_uint(qv0.z), __float_as_uint(qv0.w)};
            unsigned qf1[4] = {__float_as_uint(qv1.x), __float_as_uint(qv1.y),
                               __float_as_uint(qv1.z), __float_as_uint(qv1.w)};
#pragma unroll
            for (int nt = 0; nt < 4; nt++) {
                int r = (nt << 3) + g;
                unsigned b0 = __float_as_uint(sK[r * 68 + c]);
                unsigned b1 = __float_as_uint(sK[r * 68 + c + 4]);
                mma_tf32(s0[nt], qf0, b0, b1);
                mma_tf32(s1[nt], qf1, b0, b1);
            }
        }

        // ---- scale + causal mask ----
#pragma unroll
        for (int nt = 0; nt < 4; nt++)
#pragma unroll
            for (int c = 0; c < 4; c++) { s0[nt][c] *= cscale; s1[nt][c] *= cscale; }
        if (kt >= 4 * qb) {
            const int qg0 = q0 + rw + g;
#pragma unroll
            for (int nt = 0; nt < 4; nt++) {
                int kv = kvb + (nt << 3) + (t << 1);
                if (kv > qg0)          s0[nt][0] = -1e30f;
                if (kv + 1 > qg0)      s0[nt][1] = -1e30f;
                if (kv > qg0 + 8)      s0[nt][2] = -1e30f;
                if (kv + 1 > qg0 + 8)  s0[nt][3] = -1e30f;
                if (kv > qg0 + 16)     s1[nt][0] = -1e30f;
                if (kv + 1 > qg0 + 16) s1[nt][1] = -1e30f;
                if (kv > qg0 + 24)     s1[nt][2] = -1e30f;
                if (kv + 1 > qg0 + 24) s1[nt][3] = -1e30f;
            }
        }

        // ---- online softmax (4 row-sets) ----
#pragma unroll
        for (int sb = 0; sb < 2; sb++) {
            float (*s)[4] = sb ? s1 : s0;
            float (*o)[4] = sb ? o1 : o0;
#pragma unroll
            for (int r = 0; r < 2; r++) {
                int ix = sb * 2 + r;
                float mx = -1e30f;
#pragma unroll
                for (int nt = 0; nt < 4; nt++)
                    mx = fmaxf(mx, fmaxf(s[nt][2 * r], s[nt][2 * r + 1]));
                mx = fmaxf(mx, __shfl_xor_sync(0xffffffffu, mx, 1));
                mx = fmaxf(mx, __shfl_xor_sync(0xffffffffu, mx, 2));
                float mn = fmaxf(mr[ix], mx);
                float al = ex2_(mr[ix] - mn);
                mr[ix] = mn;
                float rs = 0.f;
#pragma unroll
                for (int nt = 0; nt < 4; nt++) {
                    float p0 = ex2_(s[nt][2 * r] - mn);
                    float p1 = ex2_(s[nt][2 * r + 1] - mn);
                    s[nt][2 * r] = p0; s[nt][2 * r + 1] = p1;
                    rs += p0 + p1;
                }
                rs += __shfl_xor_sync(0xffffffffu, rs, 1);
                rs += __shfl_xor_sync(0xffffffffu, rs, 2);
                lr[ix] = lr[ix] * al + rs;
#pragma unroll
                for (int nt = 0; nt < 8; nt++) {
                    o[nt][2 * r]     *= al;
                    o[nt][2 * r + 1] *= al;
                }
            }
        }

        // ---- store P (tf32) in a-frag order: 2 STS.64 per (sb,nt) ----
#pragma unroll
        for (int sb = 0; sb < 2; sb++) {
            float (*s)[4] = sb ? s1 : s0;
            const int mt2 = (w << 1) + sb;
#pragma unroll
            for (int nt = 0; nt < 4; nt++) {
                int base = ((mt2 << 2) + nt) * 128 + (g << 4) + ep;
                float2 lo = make_float2(__uint_as_float(f2tf(s[nt][0])),
                                        __uint_as_float(f2tf(s[nt][2])));
                float2 hi = make_float2(__uint_as_float(f2tf(s[nt][1])),
                                        __uint_as_float(f2tf(s[nt][3])));
                *(float2*)&Ps[base + (tp << 2)]       = lo;
                *(float2*)&Ps[base + ((tp + 1) << 2)] = hi;
            }
        }
        __syncwarp();

        // ---- O += P V : ks outer over 32 kv rows, LDS.128 P frags ----
#pragma unroll
        for (int ks = 0; ks < 4; ks++) {
            float4 pv0 = PsF4[((((w << 1)) << 2) + ks) * 32 + lane];
            float4 pv1 = PsF4[((((w << 1) + 1) << 2) + ks) * 32 + lane];
            unsigned pf0[4] = {__float_as_uint(pv0.x), __float_as_uint(pv0.y),
                               __float_as_uint(pv0.z), __float_as_uint(pv0.w)};
            unsigned pf1[4] = {__float_as_uint(pv1.x), __float_as_uint(pv1.y),
                               __float_as_uint(pv1.z), __float_as_uint(pv1.w)};
            const int kr = (ks << 3) + t;
#pragma unroll
            for (int nt = 0; nt < 8; nt++) {
                int nc = (nt << 3) + g;
                unsigned v0 = __float_as_uint(sV[kr * 72 + nc]);
                unsigned v1 = __float_as_uint(sV[(kr + 4) * 72 + nc]);
                mma_tf32(o0[nt], pf0, v0, v1);
                mma_tf32(o1[nt], pf1, v0, v1);
            }
        }
    }

    // ---- epilogue -> g_At [B, S, H*Dh] (plain fp32) ----
    const int b = bh >> 3, h = bh & 7;
#pragma unroll
    for (int sb = 0; sb < 2; sb++) {
        float (*o)[4] = sb ? o1 : o0;
#pragma unroll
        for (int r = 0; r < 2; r++) {
            int row = q0 + rw + (sb << 4) + (r << 3) + g;
            float inv = 1.f / lr[sb * 2 + r];
#pragma unroll
            for (int nt = 0; nt < 8; nt++) {
                int col = (h << 6) + (nt << 3) + (t << 1);
                size_t base = ((size_t)b * SEQ + row) * DM + col;
                float2 v = make_float2(o[nt][2 * r] * inv, o[nt][2 * r + 1] * inv);
                *(float2*)&g_At[base] = v;
            }
        }
    }
}

// ---------------------------------------------------------------------------
extern "C" void kernel_launch(void* const* d_in, const int* in_sizes, int n_in,
                              void* d_out, int out_size)
{
    const float* q  = (const float*)d_in[0];
    const float* k  = (const float*)d_in[1];
    const float* v  = (const float*)d_in[2];
    const float* wq = (const float*)d_in[3];
    const float* wk = (const float*)d_in[4];
    const float* wv = (const float*)d_in[5];
    const float* wo = (const float*)d_in[6];
    float* out = (float*)d_out;

    const int FLASH_SMEM = 16768 * (int)sizeof(float);   // 67072 B -> 3 CTA/SM
    cudaFuncSetAttribute(flash_tc, cudaFuncAttributeMaxDynamicSharedMemorySize,
                         FLASH_SMEM);

    dim3 pg(MTOT / 128, DM / 128, 3);        // 64 x 4 x 3
    gemm_proj<<<pg, 128>>>(q, k, v, wq, wk, wv);

    dim3 fg(SEQ / 128, BATCH * NH);          // 32 x 16
    flash_tc<<<fg, 128, FLASH_SMEM>>>();

    dim3 og(MTOT / 128, DM / 128);           // 64 x 4
    gemm_out<<<og, 128>>>(wo, out);
}